// round 12
// baseline (speedup 1.0000x reference)
#include <cuda_runtime.h>
#include <math.h>
#include <stdint.h>

// Kalman filter one-step-ahead predictions. B=512, T=256, S=32, M=4.
// TWO warps per batch (512 blocks x 64 threads). Innovation path (PH^T, S,
// Cholesky, z, downdate, means) duplicated in both warps (bitwise identical).
// The two tensor-pipe GEMMs (X^T = F*P_u ; P' = F*X + Q, tf32 3-term splits)
// split BY OUTPUT COLUMNS: warp w owns nt in {2w,2w+1} (cols 16w..16w+15),
// halving per-warp HMMA + B-fragment cvt work and doubling warps/SMSP for
// latency hiding. Q fragments live in registers. Two __syncthreads per step.

#define Bn 512
#define Tn 256
#define Sn 32
#define Mn 4
#define PL 37   // fp32 plane stride

using u64 = unsigned long long;

__device__ __forceinline__ u64 pack2(float lo, float hi) {
    u64 r; asm("mov.b64 %0,{%1,%2};" : "=l"(r) : "f"(lo), "f"(hi)); return r;
}
__device__ __forceinline__ void unpack2(u64 v, float& lo, float& hi) {
    asm("mov.b64 {%0,%1},%2;" : "=f"(lo), "=f"(hi) : "l"(v));
}
__device__ __forceinline__ u64 ffma2(u64 a, u64 b, u64 c) {
    u64 d; asm("fma.rn.f32x2 %0,%1,%2,%3;" : "=l"(d) : "l"(a), "l"(b), "l"(c)); return d;
}
__device__ __forceinline__ u64 fadd2(u64 a, u64 b) {
    u64 d; asm("add.rn.f32x2 %0,%1,%2;" : "=l"(d) : "l"(a), "l"(b)); return d;
}
__device__ __forceinline__ uint32_t tf32hi(float x) {
    uint32_t r; asm("cvt.rna.tf32.f32 %0,%1;" : "=r"(r) : "f"(x)); return r;
}
__device__ __forceinline__ void mma_tf32(float* c, const uint32_t* a,
                                         uint32_t b0, uint32_t b1) {
    asm volatile(
        "mma.sync.aligned.m16n8k8.row.col.f32.tf32.tf32.f32 "
        "{%0,%1,%2,%3},{%4,%5,%6,%7},{%8,%9},{%0,%1,%2,%3};"
        : "+f"(c[0]), "+f"(c[1]), "+f"(c[2]), "+f"(c[3])
        : "r"(a[0]), "r"(a[1]), "r"(a[2]), "r"(a[3]), "r"(b0), "r"(b1));
}

__global__ __launch_bounds__(64) void kalman_kernel(
    const float* __restrict__ obs,       // [B,T,M]
    const float* __restrict__ Fm,        // [S,S]
    const float* __restrict__ Qm,        // [S,S]
    const float* __restrict__ Hm,        // [M,S]
    const float* __restrict__ Rm,        // [M,M]
    const float* __restrict__ init_mean, // [B,S]
    const float* __restrict__ init_cov,  // [B,S,S]
    float* __restrict__ out)
{
    const int b    = blockIdx.x;
    const int tid  = threadIdx.x;
    const int wid  = tid >> 5;
    const int lane = tid & 31;
    const int g    = lane >> 2;
    const int tg   = lane & 3;

    __shared__ __align__(16) u64 sHTp[Sn * 2];   // [l*4+q] = H[q][l]
    __shared__ __align__(16) u64 sHR[4 * 17];    // hr[q*34+l] = H[q][l]
    __shared__ __align__(16) u64 sFR[Sn * 17];   // fr[j*34+l] = F[j][l]
    __shared__ __align__(16) u64 sPHT[4 * 17];   // pht[r*34+l]
    __shared__ __align__(16) float sZ[Sn * 4];
    __shared__ __align__(16) u64 sMu[16];
    __shared__ __align__(16) u64 sMp[16];
    __shared__ float sR16[16];
    __shared__ float sPu[Sn * PL];               // P_u / P' plane
    __shared__ float sXt[Sn * PL];               // X^T plane

    {
        float* frf = (float*)sFR;
        for (int idx = tid; idx < Sn * Sn; idx += 64) {
            int i = idx >> 5, l = idx & 31;
            frf[i * 34 + l] = Fm[idx];
        }
        float* hv  = (float*)sHTp;
        float* hrf = (float*)sHR;
        for (int idx = tid; idx < Mn * Sn; idx += 64) {
            int q = idx >> 5, l = idx & 31;
            float h = Hm[idx];
            hv [l * 4 + q]  = h;
            hrf[q * 34 + l] = h;
        }
        if (tid < 16) sR16[tid] = Rm[tid];
    }

    // ---- constant F A-fragments (full, both warps), hi+lo tf32 split ----
    uint32_t fh[8][4], fl[8][4];   // [mt*4+kt][reg]
#pragma unroll
    for (int mt = 0; mt < 2; ++mt)
#pragma unroll
        for (int kt = 0; kt < 4; ++kt) {
            int r0 = mt * 16 + g, c0 = kt * 8 + tg;
            float v[4];
            v[0] = Fm[r0 * Sn + c0];
            v[1] = Fm[(r0 + 8) * Sn + c0];
            v[2] = Fm[r0 * Sn + c0 + 4];
            v[3] = Fm[(r0 + 8) * Sn + c0 + 4];
#pragma unroll
            for (int j = 0; j < 4; ++j) {
                uint32_t h = tf32hi(v[j]);
                fh[mt * 4 + kt][j] = h;
                fl[mt * 4 + kt][j] = tf32hi(v[j] - __uint_as_float(h));
            }
        }

    // ---- Q accumulator fragments for THIS warp's nt tiles (registers) ----
    float qf[4][4];  // [mt*2+ntl][j]
#pragma unroll
    for (int mt = 0; mt < 2; ++mt)
#pragma unroll
        for (int ntl = 0; ntl < 2; ++ntl) {
            int nt = 2 * wid + ntl;
#pragma unroll
            for (int j = 0; j < 4; ++j) {
                int row = mt * 16 + g + 8 * (j >> 1);
                int col = nt * 8 + 2 * tg + (j & 1);
                qf[mt * 2 + ntl][j] = Qm[row * Sn + col];
            }
        }

    // per-lane state: P column `lane` (== row, symmetric), mean element
    float p[Sn];
#pragma unroll
    for (int i = 0; i < Sn; ++i)
        p[i] = init_cov[(size_t)b * (Sn * Sn) + i * Sn + lane];
    float mloc = init_mean[b * Sn + lane];

    float* muF = (float*)sMu;
    float* mpF = (float*)sMp;
    mpF[lane] = mloc;   // both warps: identical values
    __syncthreads();

    const float* yb = obs + (size_t)b * (Tn * Mn);
    float* out_means = out;
    float* out_covs  = out + (size_t)Tn * Bn * Mn;

    float4 yn = *(const float4*)yb;
    float* phtF = (float*)sPHT;

#pragma unroll 1
    for (int t = 0; t < Tn; ++t) {
        float4 yv = yn;
        int tnext = (t + 1 < Tn) ? (t + 1) : (Tn - 1);
        yn = *(const float4*)(yb + 4 * tnext);

        // ======== innovation path: duplicated, bitwise identical ========
        // mm[q] on lane q (q<4): dot(H row q, m_p)
        float mmv = 0.f;
        {
            u64 accm0 = 0ull, accm1 = 0ull;
            const u64* hq = &sHR[(lane & 3) * 17];
#pragma unroll
            for (int c = 0; c < 8; ++c) {
                accm0 = ffma2(hq[2 * c + 0], sMp[2 * c + 0], accm0);
                accm1 = ffma2(hq[2 * c + 1], sMp[2 * c + 1], accm1);
            }
            u64 accm = fadd2(accm0, accm1);
            float alo, ahi; unpack2(accm, alo, ahi);
            mmv = alo + ahi;
        }

        // phtt = row `lane` of P*H^T (4 split chains)
        u64 a00 = 0ull, a01 = 0ull, a10 = 0ull, a11 = 0ull;
#pragma unroll
        for (int l = 0; l < Sn; l += 2) {
            ulonglong2 h0 = *(const ulonglong2*)&sHTp[l * 2];
            ulonglong2 h1 = *(const ulonglong2*)&sHTp[(l + 1) * 2];
            u64 ps0 = pack2(p[l], p[l]);
            u64 ps1 = pack2(p[l + 1], p[l + 1]);
            a00 = ffma2(ps0, h0.x, a00); a10 = ffma2(ps0, h0.y, a10);
            a01 = ffma2(ps1, h1.x, a01); a11 = ffma2(ps1, h1.y, a11);
        }
        u64 ph2a = fadd2(a00, a01);
        u64 ph2b = fadd2(a10, a11);
        float ph0, ph1, phh2, ph3;
        unpack2(ph2a, ph0, ph1);
        unpack2(ph2b, phh2, ph3);
        phtF[0 * 34 + lane] = ph0;   // duplicated identical stores
        phtF[1 * 34 + lane] = ph1;
        phtF[2 * 34 + lane] = phh2;
        phtF[3 * 34 + lane] = ph3;

        float c0 = __shfl_sync(0xffffffffu, mmv, 0);
        float c1 = __shfl_sync(0xffffffffu, mmv, 1);
        float c2 = __shfl_sync(0xffffffffu, mmv, 2);
        float c3 = __shfl_sync(0xffffffffu, mmv, 3);
        if (tid == 0)
            *(float4*)&out_means[((size_t)t * Bn + b) * 4] = make_float4(c0, c1, c2, c3);
        float r0 = yv.x - c0, r1 = yv.y - c1, r2 = yv.z - c2, r3 = yv.w - c3;
        __syncwarp();

        // S = H*(PH^T) + R
        int q = (lane >> 2) & 3, r = lane & 3;
        float sv;
        {
            u64 acc0 = 0ull, acc1 = 0ull;
            const u64* hq = &sHR [q * 17];
            const u64* pr = &sPHT[r * 17];
#pragma unroll
            for (int c = 0; c < 8; ++c) {
                acc0 = ffma2(hq[2 * c + 0], pr[2 * c + 0], acc0);
                acc1 = ffma2(hq[2 * c + 1], pr[2 * c + 1], acc1);
            }
            u64 acc = fadd2(acc0, acc1);
            float alo, ahi; unpack2(acc, alo, ahi);
            sv = sR16[(q << 2) | r] + (alo + ahi);
        }
        if (tid < 16)
            out_covs[((size_t)t * Bn + b) * 16 + tid] = sv;

        if (t == Tn - 1) break;

        // broadcast S, rsqrt 4x4 Cholesky (redundant per lane & warp)
        float s00 = __shfl_sync(0xffffffffu, sv, 0);
        float s10 = __shfl_sync(0xffffffffu, sv, 4);
        float s11 = __shfl_sync(0xffffffffu, sv, 5);
        float s20 = __shfl_sync(0xffffffffu, sv, 8);
        float s21 = __shfl_sync(0xffffffffu, sv, 9);
        float s22 = __shfl_sync(0xffffffffu, sv, 10);
        float s30 = __shfl_sync(0xffffffffu, sv, 12);
        float s31 = __shfl_sync(0xffffffffu, sv, 13);
        float s32 = __shfl_sync(0xffffffffu, sv, 14);
        float s33 = __shfl_sync(0xffffffffu, sv, 15);
        float i0 = rsqrtf(s00);
        float L10 = s10 * i0, L20 = s20 * i0, L30 = s30 * i0;
        float i1 = rsqrtf(s11 - L10 * L10);
        float L21 = (s21 - L20 * L10) * i1;
        float L31 = (s31 - L30 * L10) * i1;
        float i2 = rsqrtf(s22 - L20 * L20 - L21 * L21);
        float L32 = (s32 - L30 * L20 - L31 * L21) * i2;
        float i3 = rsqrtf(s33 - L30 * L30 - L31 * L31 - L32 * L32);

        float z0 = ph0 * i0;
        float z1 = (ph1 - L10 * z0) * i1;
        float z2 = (phh2 - L20 * z0 - L21 * z1) * i2;
        float z3 = (ph3 - L30 * z0 - L31 * z1 - L32 * z2) * i3;
        float k3 = z3 * i3;
        float k2 = (z2 - L32 * k3) * i2;
        float k1 = (z1 - L21 * k2 - L31 * k3) * i1;
        float k0 = (z0 - L10 * k1 - L20 * k2 - L30 * k3) * i0;

        *(float4*)&sZ[lane * 4] = make_float4(z0, z1, z2, z3);
        __syncwarp();

        mloc = fmaf(k0, r0, fmaf(k1, r1, fmaf(k2, r2, fmaf(k3, r3, mloc))));
        muF[lane] = mloc;

        // symmetric rank-4 downdate
#pragma unroll
        for (int i = 0; i < Sn; ++i) {
            float4 zi = *(const float4*)&sZ[i * 4];
            float d = zi.x * z0;
            d = fmaf(zi.y, z1, d);
            d = fmaf(zi.z, z2, d);
            d = fmaf(zi.w, z3, d);
            p[i] -= d;
        }

        // publish P_u plane (both warps, identical values -> benign race;
        // each warp reads only its own writes before the next barrier)
#pragma unroll
        for (int i = 0; i < Sn; ++i)
            sPu[i * PL + lane] = p[i];
        __syncwarp();

        // ======== MMA1: X^T = F * P_u, THIS warp's nt tiles ========
        float xac[4][4];
#pragma unroll
        for (int ti = 0; ti < 4; ++ti)
#pragma unroll
            for (int j = 0; j < 4; ++j) xac[ti][j] = 0.f;
#pragma unroll
        for (int kt = 0; kt < 4; ++kt) {
#pragma unroll
            for (int ntl = 0; ntl < 2; ++ntl) {
                int nt = 2 * wid + ntl;
                float rb0 = sPu[(kt * 8 + tg) * PL + nt * 8 + g];
                float rb1 = sPu[(kt * 8 + tg + 4) * PL + nt * 8 + g];
                uint32_t bh0 = tf32hi(rb0);
                uint32_t bh1 = tf32hi(rb1);
                uint32_t bl0 = tf32hi(rb0 - __uint_as_float(bh0));
                uint32_t bl1 = tf32hi(rb1 - __uint_as_float(bh1));
#pragma unroll
                for (int mt = 0; mt < 2; ++mt) {
                    mma_tf32(xac[mt * 2 + ntl], fh[mt * 4 + kt], bh0, bh1);
                    mma_tf32(xac[mt * 2 + ntl], fh[mt * 4 + kt], bl0, bl1);
                    mma_tf32(xac[mt * 2 + ntl], fl[mt * 4 + kt], bh0, bh1);
                }
            }
        }
#pragma unroll
        for (int ti = 0; ti < 4; ++ti) {
            int mt = ti >> 1, ntl = ti & 1;
            int rr = mt * 16 + g, cc = (2 * wid + ntl) * 8 + 2 * tg;
            sXt[rr * PL + cc]           = xac[ti][0];
            sXt[rr * PL + cc + 1]       = xac[ti][1];
            sXt[(rr + 8) * PL + cc]     = xac[ti][2];
            sXt[(rr + 8) * PL + cc + 1] = xac[ti][3];
        }
        __syncthreads();   // BAR1: X^T cols from both warps complete

        // mean predict (duplicated)
        float mp;
        {
            u64 acc0 = 0ull, acc1 = 0ull;
            const u64* frw = &sFR[lane * 17];
#pragma unroll
            for (int c = 0; c < 8; ++c) {
                acc0 = ffma2(frw[2 * c + 0], sMu[2 * c + 0], acc0);
                acc1 = ffma2(frw[2 * c + 1], sMu[2 * c + 1], acc1);
            }
            u64 acc = fadd2(acc0, acc1);
            float alo, ahi; unpack2(acc, alo, ahi);
            mp = alo + ahi;
        }

        // ======== MMA2: P' = F * X + Q, THIS warp's nt tiles ========
        float pac[4][4];
#pragma unroll
        for (int ti = 0; ti < 4; ++ti)
#pragma unroll
            for (int j = 0; j < 4; ++j) pac[ti][j] = qf[ti][j];
#pragma unroll
        for (int kt = 0; kt < 4; ++kt) {
#pragma unroll
            for (int ntl = 0; ntl < 2; ++ntl) {
                int nt = 2 * wid + ntl;
                float rb0 = sXt[(nt * 8 + g) * PL + kt * 8 + tg];
                float rb1 = sXt[(nt * 8 + g) * PL + kt * 8 + tg + 4];
                uint32_t bh0 = tf32hi(rb0);
                uint32_t bh1 = tf32hi(rb1);
                uint32_t bl0 = tf32hi(rb0 - __uint_as_float(bh0));
                uint32_t bl1 = tf32hi(rb1 - __uint_as_float(bh1));
#pragma unroll
                for (int mt = 0; mt < 2; ++mt) {
                    mma_tf32(pac[mt * 2 + ntl], fh[mt * 4 + kt], bh0, bh1);
                    mma_tf32(pac[mt * 2 + ntl], fh[mt * 4 + kt], bl0, bl1);
                    mma_tf32(pac[mt * 2 + ntl], fl[mt * 4 + kt], bh0, bh1);
                }
            }
        }
#pragma unroll
        for (int ti = 0; ti < 4; ++ti) {
            int mt = ti >> 1, ntl = ti & 1;
            int rr = mt * 16 + g, cc = (2 * wid + ntl) * 8 + 2 * tg;
            sPu[rr * PL + cc]           = pac[ti][0];
            sPu[rr * PL + cc + 1]       = pac[ti][1];
            sPu[(rr + 8) * PL + cc]     = pac[ti][2];
            sPu[(rr + 8) * PL + cc + 1] = pac[ti][3];
        }

        mloc = mp;
        mpF[lane] = mp;    // duplicated identical stores
        __syncthreads();   // BAR2: P' cols from both warps complete

        // reload per-lane column of P'
#pragma unroll
        for (int i = 0; i < Sn; ++i)
            p[i] = sPu[i * PL + lane];
    }
}

extern "C" void kernel_launch(void* const* d_in, const int* in_sizes, int n_in,
                              void* d_out, int out_size)
{
    const float* obs       = (const float*)d_in[0];
    const float* Fm        = (const float*)d_in[1];
    const float* Qm        = (const float*)d_in[2];
    const float* Hm        = (const float*)d_in[3];
    const float* Rm        = (const float*)d_in[4];
    const float* init_mean = (const float*)d_in[5];
    const float* init_cov  = (const float*)d_in[6];
    float* out = (float*)d_out;

    kalman_kernel<<<Bn, 64>>>(obs, Fm, Qm, Hm, Rm, init_mean, init_cov, out);
}

// round 13
// speedup vs baseline: 1.1989x; 1.1989x over previous
#include <cuda_runtime.h>
#include <math.h>
#include <stdint.h>

// Kalman filter one-step-ahead predictions. B=512, T=256, S=32, M=4.
// Warp-per-batch (32x512). Tensor-pipe covariance propagation restructured as
//   P' = F*P*F^T + Q - W*W^T,   W = F*Z  (Z = whitened rank-4 update, 32x4)
// so MMA1 (Yt = F*P) depends ONLY on the previous P plane and overlaps the
// serial innovation chain (PH^T, S, Cholesky, z). The rank-4 correction is
// applied to MMA2's accumulator fragments. tf32 hi/lo via LOP masks (lat 4).

#define Bn 512
#define Tn 256
#define Sn 32
#define Mn 4
#define PL 37   // fp32 plane stride (conflict-free)

using u64 = unsigned long long;

__device__ __forceinline__ u64 pack2(float lo, float hi) {
    u64 r; asm("mov.b64 %0,{%1,%2};" : "=l"(r) : "f"(lo), "f"(hi)); return r;
}
__device__ __forceinline__ void unpack2(u64 v, float& lo, float& hi) {
    asm("mov.b64 {%0,%1},%2;" : "=f"(lo), "=f"(hi) : "l"(v));
}
__device__ __forceinline__ u64 ffma2(u64 a, u64 b, u64 c) {
    u64 d; asm("fma.rn.f32x2 %0,%1,%2,%3;" : "=l"(d) : "l"(a), "l"(b), "l"(c)); return d;
}
__device__ __forceinline__ u64 fadd2(u64 a, u64 b) {
    u64 d; asm("add.rn.f32x2 %0,%1,%2;" : "=l"(d) : "l"(a), "l"(b)); return d;
}
// tf32 split via bit masks (LOP3, lat 4) instead of cvt chains
__device__ __forceinline__ void split_tf32(float x, uint32_t& h, uint32_t& l) {
    h = __float_as_uint(x) & 0xffffe000u;
    float r = x - __uint_as_float(h);
    l = __float_as_uint(r) & 0xffffe000u;
}
__device__ __forceinline__ void mma_tf32(float* c, const uint32_t* a,
                                         uint32_t b0, uint32_t b1) {
    asm volatile(
        "mma.sync.aligned.m16n8k8.row.col.f32.tf32.tf32.f32 "
        "{%0,%1,%2,%3},{%4,%5,%6,%7},{%8,%9},{%0,%1,%2,%3};"
        : "+f"(c[0]), "+f"(c[1]), "+f"(c[2]), "+f"(c[3])
        : "r"(a[0]), "r"(a[1]), "r"(a[2]), "r"(a[3]), "r"(b0), "r"(b1));
}

__global__ __launch_bounds__(32) void kalman_kernel(
    const float* __restrict__ obs,       // [B,T,M]
    const float* __restrict__ Fm,        // [S,S]
    const float* __restrict__ Qm,        // [S,S]
    const float* __restrict__ Hm,        // [M,S]
    const float* __restrict__ Rm,        // [M,M]
    const float* __restrict__ init_mean, // [B,S]
    const float* __restrict__ init_cov,  // [B,S,S]
    float* __restrict__ out)
{
    const int b    = blockIdx.x;
    const int lane = threadIdx.x;
    const int g    = lane >> 2;
    const int tg   = lane & 3;

    __shared__ __align__(16) u64 sHTp[Sn * 2];   // [l*4+q] = H[q][l]
    __shared__ __align__(16) u64 sHR[4 * 17];    // hr[q*34+l] = H[q][l]
    __shared__ __align__(16) u64 sFR[Sn * 17];   // fr[j*34+l] = F[j][l]
    __shared__ __align__(16) u64 sPHT[4 * 17];   // pht[r*34+l]
    __shared__ __align__(16) float sZ[Sn * 4];   // whitened z rows
    __shared__ __align__(16) float sW[Sn * 4];   // W = F*Z rows
    __shared__ __align__(16) u64 sMu[16];
    __shared__ __align__(16) u64 sMp[16];
    __shared__ float sR16[16];
    __shared__ float sQf[32 * 33];               // Q acc-layout fragments
    __shared__ float sPu[Sn * PL];               // P plane (persistent)
    __shared__ float sXt[Sn * PL];               // Yt = F*P plane

    {
        float* frf = (float*)sFR;
        for (int idx = lane; idx < Sn * Sn; idx += 32) {
            int i = idx >> 5, l = idx & 31;
            frf[i * 34 + l] = Fm[idx];
        }
        float* hv  = (float*)sHTp;
        float* hrf = (float*)sHR;
        for (int idx = lane; idx < Mn * Sn; idx += 32) {
            int q = idx >> 5, l = idx & 31;
            float h = Hm[idx];
            hv [l * 4 + q]  = h;
            hrf[q * 34 + l] = h;
        }
        if (lane < 16) sR16[lane] = Rm[lane];
        for (int ti = 0; ti < 8; ++ti) {
            int mt = ti >> 2, nt = ti & 3;
#pragma unroll
            for (int j = 0; j < 4; ++j) {
                int row = mt * 16 + g + 8 * (j >> 1);
                int col = nt * 8 + 2 * tg + (j & 1);
                sQf[(ti * 4 + j) * 33 + lane] = Qm[row * Sn + col];
            }
        }
    }

    // ---- constant F A-fragments, hi+lo mask split ----
    uint32_t fh[8][4], fl[8][4];
#pragma unroll
    for (int mt = 0; mt < 2; ++mt)
#pragma unroll
        for (int kt = 0; kt < 4; ++kt) {
            int r0 = mt * 16 + g, c0 = kt * 8 + tg;
            float v[4];
            v[0] = Fm[r0 * Sn + c0];
            v[1] = Fm[(r0 + 8) * Sn + c0];
            v[2] = Fm[r0 * Sn + c0 + 4];
            v[3] = Fm[(r0 + 8) * Sn + c0 + 4];
#pragma unroll
            for (int j = 0; j < 4; ++j)
                split_tf32(v[j], fh[mt * 4 + kt][j], fl[mt * 4 + kt][j]);
        }

    // per-lane state + initial P plane
    float p[Sn];
#pragma unroll
    for (int i = 0; i < Sn; ++i) {
        p[i] = init_cov[(size_t)b * (Sn * Sn) + i * Sn + lane];
        sPu[i * PL + lane] = p[i];
    }
    float mloc = init_mean[b * Sn + lane];

    float* muF = (float*)sMu;
    float* mpF = (float*)sMp;
    mpF[lane] = mloc;
    __syncwarp();

    const float* yb = obs + (size_t)b * (Tn * Mn);
    float* out_means = out;
    float* out_covs  = out + (size_t)Tn * Bn * Mn;

    float4 yn = *(const float4*)yb;
    float* phtF = (float*)sPHT;

#pragma unroll 1
    for (int t = 0; t < Tn; ++t) {
        float4 yv = yn;
        int tnext = (t + 1 < Tn) ? (t + 1) : (Tn - 1);
        yn = *(const float4*)(yb + 4 * tnext);

        // ======== MMA1: Yt = F * P (independent of innovation) ========
        float yac[8][4];
#pragma unroll
        for (int ti = 0; ti < 8; ++ti)
#pragma unroll
            for (int j = 0; j < 4; ++j) yac[ti][j] = 0.f;
#pragma unroll
        for (int kt = 0; kt < 4; ++kt) {
#pragma unroll
            for (int nt = 0; nt < 4; ++nt) {
                float rb0 = sPu[(kt * 8 + tg) * PL + nt * 8 + g];
                float rb1 = sPu[(kt * 8 + tg + 4) * PL + nt * 8 + g];
                uint32_t bh0, bl0, bh1, bl1;
                split_tf32(rb0, bh0, bl0);
                split_tf32(rb1, bh1, bl1);
#pragma unroll
                for (int mt = 0; mt < 2; ++mt) {
                    mma_tf32(yac[mt * 4 + nt], fh[mt * 4 + kt], bh0, bh1);
                    mma_tf32(yac[mt * 4 + nt], fh[mt * 4 + kt], bl0, bl1);
                    mma_tf32(yac[mt * 4 + nt], fl[mt * 4 + kt], bh0, bh1);
                }
            }
        }
#pragma unroll
        for (int ti = 0; ti < 8; ++ti) {
            int mt = ti >> 2, nt = ti & 3;
            int rr = mt * 16 + g, cc = nt * 8 + 2 * tg;
            sXt[rr * PL + cc]           = yac[ti][0];
            sXt[rr * PL + cc + 1]       = yac[ti][1];
            sXt[(rr + 8) * PL + cc]     = yac[ti][2];
            sXt[(rr + 8) * PL + cc + 1] = yac[ti][3];
        }

        // ======== innovation (uses p registers = column of P) ========
        float mmv = 0.f;
        {
            u64 accm0 = 0ull, accm1 = 0ull;
            const u64* hq = &sHR[(lane & 3) * 17];
#pragma unroll
            for (int c = 0; c < 8; ++c) {
                accm0 = ffma2(hq[2 * c + 0], sMp[2 * c + 0], accm0);
                accm1 = ffma2(hq[2 * c + 1], sMp[2 * c + 1], accm1);
            }
            u64 accm = fadd2(accm0, accm1);
            float alo, ahi; unpack2(accm, alo, ahi);
            mmv = alo + ahi;
        }

        u64 a00 = 0ull, a01 = 0ull, a10 = 0ull, a11 = 0ull;
#pragma unroll
        for (int l = 0; l < Sn; l += 2) {
            ulonglong2 h0 = *(const ulonglong2*)&sHTp[l * 2];
            ulonglong2 h1 = *(const ulonglong2*)&sHTp[(l + 1) * 2];
            u64 ps0 = pack2(p[l], p[l]);
            u64 ps1 = pack2(p[l + 1], p[l + 1]);
            a00 = ffma2(ps0, h0.x, a00); a10 = ffma2(ps0, h0.y, a10);
            a01 = ffma2(ps1, h1.x, a01); a11 = ffma2(ps1, h1.y, a11);
        }
        u64 ph2a = fadd2(a00, a01);
        u64 ph2b = fadd2(a10, a11);
        float ph0, ph1, phh2, ph3;
        unpack2(ph2a, ph0, ph1);
        unpack2(ph2b, phh2, ph3);
        phtF[0 * 34 + lane] = ph0;
        phtF[1 * 34 + lane] = ph1;
        phtF[2 * 34 + lane] = phh2;
        phtF[3 * 34 + lane] = ph3;

        float c0 = __shfl_sync(0xffffffffu, mmv, 0);
        float c1 = __shfl_sync(0xffffffffu, mmv, 1);
        float c2 = __shfl_sync(0xffffffffu, mmv, 2);
        float c3 = __shfl_sync(0xffffffffu, mmv, 3);
        if (lane == 0)
            *(float4*)&out_means[((size_t)t * Bn + b) * 4] = make_float4(c0, c1, c2, c3);
        float r0 = yv.x - c0, r1 = yv.y - c1, r2 = yv.z - c2, r3 = yv.w - c3;
        __syncwarp();   // pht + sXt visible

        int q = (lane >> 2) & 3, r = lane & 3;
        float sv;
        {
            u64 acc0 = 0ull, acc1 = 0ull;
            const u64* hq = &sHR [q * 17];
            const u64* pr = &sPHT[r * 17];
#pragma unroll
            for (int c = 0; c < 8; ++c) {
                acc0 = ffma2(hq[2 * c + 0], pr[2 * c + 0], acc0);
                acc1 = ffma2(hq[2 * c + 1], pr[2 * c + 1], acc1);
            }
            u64 acc = fadd2(acc0, acc1);
            float alo, ahi; unpack2(acc, alo, ahi);
            sv = sR16[(q << 2) | r] + (alo + ahi);
        }
        if (lane < 16)
            out_covs[((size_t)t * Bn + b) * 16 + lane] = sv;

        if (t == Tn - 1) break;

        float s00 = __shfl_sync(0xffffffffu, sv, 0);
        float s10 = __shfl_sync(0xffffffffu, sv, 4);
        float s11 = __shfl_sync(0xffffffffu, sv, 5);
        float s20 = __shfl_sync(0xffffffffu, sv, 8);
        float s21 = __shfl_sync(0xffffffffu, sv, 9);
        float s22 = __shfl_sync(0xffffffffu, sv, 10);
        float s30 = __shfl_sync(0xffffffffu, sv, 12);
        float s31 = __shfl_sync(0xffffffffu, sv, 13);
        float s32 = __shfl_sync(0xffffffffu, sv, 14);
        float s33 = __shfl_sync(0xffffffffu, sv, 15);
        float i0 = rsqrtf(s00);
        float L10 = s10 * i0, L20 = s20 * i0, L30 = s30 * i0;
        float i1 = rsqrtf(s11 - L10 * L10);
        float L21 = (s21 - L20 * L10) * i1;
        float L31 = (s31 - L30 * L10) * i1;
        float i2 = rsqrtf(s22 - L20 * L20 - L21 * L21);
        float L32 = (s32 - L30 * L20 - L31 * L21) * i2;
        float i3 = rsqrtf(s33 - L30 * L30 - L31 * L31 - L32 * L32);

        float z0 = ph0 * i0;
        float z1 = (ph1 - L10 * z0) * i1;
        float z2 = (phh2 - L20 * z0 - L21 * z1) * i2;
        float z3 = (ph3 - L30 * z0 - L31 * z1 - L32 * z2) * i3;
        float k3 = z3 * i3;
        float k2 = (z2 - L32 * k3) * i2;
        float k1 = (z1 - L21 * k2 - L31 * k3) * i1;
        float k0 = (z0 - L10 * k1 - L20 * k2 - L30 * k3) * i0;

        *(float4*)&sZ[lane * 4] = make_float4(z0, z1, z2, z3);
        __syncwarp();

        mloc = fmaf(k0, r0, fmaf(k1, r1, fmaf(k2, r2, fmaf(k3, r3, mloc))));
        muF[lane] = mloc;

        // ---- W = F * Z (per-lane row of W; Z rows in sZ) ----
        float w0 = 0.f, w1 = 0.f, w2 = 0.f, w3 = 0.f;
        {
            const u64* frw = &sFR[lane * 17];
#pragma unroll
            for (int c = 0; c < 16; ++c) {
                float f0, f1; unpack2(frw[c], f0, f1);
                float4 za = *(const float4*)&sZ[(2 * c) * 4];
                float4 zb = *(const float4*)&sZ[(2 * c + 1) * 4];
                w0 = fmaf(f0, za.x, w0); w1 = fmaf(f0, za.y, w1);
                w2 = fmaf(f0, za.z, w2); w3 = fmaf(f0, za.w, w3);
                w0 = fmaf(f1, zb.x, w0); w1 = fmaf(f1, zb.y, w1);
                w2 = fmaf(f1, zb.z, w2); w3 = fmaf(f1, zb.w, w3);
            }
        }
        *(float4*)&sW[lane * 4] = make_float4(w0, w1, w2, w3);
        __syncwarp();   // sW + sXt(all lanes) visible for MMA2/correction

        // ---- mean predict ----
        float mp;
        {
            u64 acc0 = 0ull, acc1 = 0ull;
            const u64* frw = &sFR[lane * 17];
#pragma unroll
            for (int c = 0; c < 8; ++c) {
                acc0 = ffma2(frw[2 * c + 0], sMu[2 * c + 0], acc0);
                acc1 = ffma2(frw[2 * c + 1], sMu[2 * c + 1], acc1);
            }
            u64 acc = fadd2(acc0, acc1);
            float alo, ahi; unpack2(acc, alo, ahi);
            mp = alo + ahi;
        }

        // ======== MMA2: P' = F * Y + Q, Y[k][n] = Yt[n][k] ========
        float pac[8][4];
#pragma unroll
        for (int ti = 0; ti < 8; ++ti)
#pragma unroll
            for (int j = 0; j < 4; ++j)
                pac[ti][j] = sQf[(ti * 4 + j) * 33 + lane];
#pragma unroll
        for (int kt = 0; kt < 4; ++kt) {
#pragma unroll
            for (int nt = 0; nt < 4; ++nt) {
                float rb0 = sXt[(nt * 8 + g) * PL + kt * 8 + tg];
                float rb1 = sXt[(nt * 8 + g) * PL + kt * 8 + tg + 4];
                uint32_t bh0, bl0, bh1, bl1;
                split_tf32(rb0, bh0, bl0);
                split_tf32(rb1, bh1, bl1);
#pragma unroll
                for (int mt = 0; mt < 2; ++mt) {
                    mma_tf32(pac[mt * 4 + nt], fh[mt * 4 + kt], bh0, bh1);
                    mma_tf32(pac[mt * 4 + nt], fh[mt * 4 + kt], bl0, bl1);
                    mma_tf32(pac[mt * 4 + nt], fl[mt * 4 + kt], bh0, bh1);
                }
            }
        }

        // ---- rank-4 correction on fragments: pac -= W_row . W_col ----
#pragma unroll
        for (int ti = 0; ti < 8; ++ti) {
            int mt = ti >> 2, nt = ti & 3;
            int rr = mt * 16 + g, cc = nt * 8 + 2 * tg;
            float4 wr0 = *(const float4*)&sW[rr * 4];
            float4 wr1 = *(const float4*)&sW[(rr + 8) * 4];
            float4 wc0 = *(const float4*)&sW[cc * 4];
            float4 wc1 = *(const float4*)&sW[(cc + 1) * 4];
            float d00 = wr0.x * wc0.x; d00 = fmaf(wr0.y, wc0.y, d00);
            d00 = fmaf(wr0.z, wc0.z, d00); d00 = fmaf(wr0.w, wc0.w, d00);
            float d01 = wr0.x * wc1.x; d01 = fmaf(wr0.y, wc1.y, d01);
            d01 = fmaf(wr0.z, wc1.z, d01); d01 = fmaf(wr0.w, wc1.w, d01);
            float d10 = wr1.x * wc0.x; d10 = fmaf(wr1.y, wc0.y, d10);
            d10 = fmaf(wr1.z, wc0.z, d10); d10 = fmaf(wr1.w, wc0.w, d10);
            float d11 = wr1.x * wc1.x; d11 = fmaf(wr1.y, wc1.y, d11);
            d11 = fmaf(wr1.z, wc1.z, d11); d11 = fmaf(wr1.w, wc1.w, d11);
            pac[ti][0] -= d00;
            pac[ti][1] -= d01;
            pac[ti][2] -= d10;
            pac[ti][3] -= d11;
        }

        // store P' plane
#pragma unroll
        for (int ti = 0; ti < 8; ++ti) {
            int mt = ti >> 2, nt = ti & 3;
            int rr = mt * 16 + g, cc = nt * 8 + 2 * tg;
            sPu[rr * PL + cc]           = pac[ti][0];
            sPu[rr * PL + cc + 1]       = pac[ti][1];
            sPu[(rr + 8) * PL + cc]     = pac[ti][2];
            sPu[(rr + 8) * PL + cc + 1] = pac[ti][3];
        }

        mloc = mp;
        mpF[lane] = mp;
        __syncwarp();

        // reload per-lane column of P'
#pragma unroll
        for (int i = 0; i < Sn; ++i)
            p[i] = sPu[i * PL + lane];
    }
}

extern "C" void kernel_launch(void* const* d_in, const int* in_sizes, int n_in,
                              void* d_out, int out_size)
{
    const float* obs       = (const float*)d_in[0];
    const float* Fm        = (const float*)d_in[1];
    const float* Qm        = (const float*)d_in[2];
    const float* Hm        = (const float*)d_in[3];
    const float* Rm        = (const float*)d_in[4];
    const float* init_mean = (const float*)d_in[5];
    const float* init_cov  = (const float*)d_in[6];
    float* out = (float*)d_out;

    kalman_kernel<<<Bn, 32>>>(obs, Fm, Qm, Hm, Rm, init_mean, init_cov, out);
}